// round 16
// baseline (speedup 1.0000x reference)
#include <cuda_runtime.h>
#include <cuda_bf16.h>
#include <cuda_fp16.h>
#include <cstdint>

#define NB   64
#define LL   128
#define DIN  128
#define DH   128
#define PITCHB 272      // b16 tile row pitch in BYTES (136 elems)
#define LOG2E 1.4426950408889634f

extern __shared__ char dynsm[];

__device__ __half g_W3f16[DH * DIN * DH];    // [h][f][k], pre-scaled by log2(e)
__device__ __half g_h2f16[NB * LL * DH];     // [n][l][k]

// ---------------------------------------------------------------------------
__device__ __forceinline__ uint32_t smem_u32(const void* p) {
    uint32_t a;
    asm("{ .reg .u64 t; cvta.to.shared.u64 t, %1; cvt.u32.u64 %0, t; }" : "=r"(a) : "l"(p));
    return a;
}
__device__ __forceinline__ float fex2(float a) {
    float r;
    asm("ex2.approx.ftz.f32 %0, %1;" : "=f"(r) : "f"(a));
    return r;
}
__device__ __forceinline__ void mma16816h(float* c, const uint32_t* a, const uint32_t* b) {
    asm volatile(
        "mma.sync.aligned.m16n8k16.row.col.f32.f16.f16.f32 "
        "{%0,%1,%2,%3}, {%4,%5,%6,%7}, {%8,%9}, {%0,%1,%2,%3};"
        : "+f"(c[0]), "+f"(c[1]), "+f"(c[2]), "+f"(c[3])
        : "r"(a[0]), "r"(a[1]), "r"(a[2]), "r"(a[3]), "r"(b[0]), "r"(b[1]));
}
__device__ __forceinline__ void ldsm4(uint32_t addr, uint32_t r[4]) {
    asm volatile("ldmatrix.sync.aligned.m8n8.x4.shared.b16 {%0,%1,%2,%3}, [%4];"
                 : "=r"(r[0]), "=r"(r[1]), "=r"(r[2]), "=r"(r[3]) : "r"(addr));
}
#define CP_ASYNC16(dst32, srcgen) \
    asm volatile("cp.async.cg.shared.global [%0], [%1], 16;" \
                 :: "r"(dst32), "l"(__cvta_generic_to_global(srcgen)) : "memory")
#define CP_COMMIT()  asm volatile("cp.async.commit_group;" ::: "memory")
#define CP_WAIT0()   asm volatile("cp.async.wait_group 0;" ::: "memory")

__device__ __forceinline__ uint32_t pack_h2(float a, float b) {
    __half2 h = __floats2half2_rn(a, b);
    return *reinterpret_cast<uint32_t*>(&h);
}

// ---------------------------------------------------------------------------
// k01: merged preprocessing (identical to R14, which passed).
// ---------------------------------------------------------------------------
#define K1_P0   0
#define K1_P1   17408
#define K1_P2   34816
#define STG_OFF 69632
#define K01_SMEM 102656

__global__ void __launch_bounds__(256, 1) k01(
    const float* __restrict__ W3, const float* __restrict__ W1, const float* __restrict__ W2,
    const float* __restrict__ x,  const float* __restrict__ b1, const float* __restrict__ b2)
{
    char* sm = dynsm;
    const int bx = blockIdx.x, tid = threadIdx.x;

    if (bx >= 128) {
        float* s = reinterpret_cast<float*>(sm);   // [32][129]
        int h = (bx - 128) >> 2, zc = (bx - 128) & 3;
        const int kbase = zc * 32;
        const float* src = W3 + (size_t)kbase * (DIN * DH) + h * DIN;
        for (int i = tid; i < 4096; i += 256) {
            int kk = i >> 7, f = i & 127;
            s[kk * 129 + f] = src[(size_t)kk * (DIN * DH) + f];
        }
        __syncthreads();
        __half* dst = g_W3f16 + (size_t)h * DIN * DH;
        for (int i = tid; i < 4096; i += 256) {
            int f = i >> 5, kk = i & 31;
            dst[(size_t)f * 128 + kbase + kk] = __float2half(s[kk * 129 + f] * LOG2E);
        }
        return;
    }

    const uint32_t sb = smem_u32(sm);
    const int lane = tid & 31, wid = tid >> 5;
    const int g = lane >> 2, tq = lane & 3;
    const int jh = wid & 3, lw = wid >> 2;
    const int j0 = jh * 32, l0w = lw * 32;
    const int n = bx >> 1, lh = bx & 1;
    float* stg = reinterpret_cast<float*>(sm + STG_OFF);

    #pragma unroll
    for (int cch = 0; cch < 2; ++cch) {
        for (int i = tid; i < 8192; i += 256) {
            int kk = i >> 7, j = i & 127;
            stg[kk * 129 + j] = W1[(size_t)(cch * 64 + kk) * DH + j];
        }
        __syncthreads();
        for (int i = tid; i < 8192; i += 256) {
            int j = i >> 6, kk = i & 63;
            *reinterpret_cast<__half*>(sm + K1_P2 + j * PITCHB + (cch * 64 + kk) * 2) =
                __float2half(stg[kk * 129 + j]);
        }
        __syncthreads();
    }
    {
        const float* xp = x + ((size_t)n * LL + lh * 64) * DIN;
        for (int i = tid; i < 4096; i += 256) {
            int r = i >> 6, c2 = i & 63;
            float2 v = reinterpret_cast<const float2*>(xp + (size_t)r * DIN)[c2];
            *reinterpret_cast<uint32_t*>(sm + K1_P0 + r * PITCHB + c2 * 4) = pack_h2(v.x, v.y);
        }
    }
    __syncthreads();

    const int rr = lane & 7, mm = lane >> 3;
    const uint32_t aoffA = (uint32_t)((l0w + (mm & 1) * 8 + rr) * PITCHB + (mm >> 1) * 16);
    const uint32_t aoffB = (uint32_t)((j0 + (mm >> 1) * 8 + rr) * PITCHB + (mm & 1) * 16);

    float acc[2][4][4];
    #pragma unroll
    for (int mt = 0; mt < 2; ++mt)
        #pragma unroll
        for (int nt = 0; nt < 4; ++nt)
            #pragma unroll
            for (int q = 0; q < 4; ++q) acc[mt][nt][q] = 0.0f;

    {
        const uint32_t aA = sb + K1_P0 + aoffA;
        const uint32_t aB = sb + K1_P2 + aoffB;
        #pragma unroll
        for (int ks = 0; ks < 8; ++ks) {
            const uint32_t ko = ks * 32;
            uint32_t a0[4], a1[4], b0[4], b1r[4];
            ldsm4(aA + ko, a0);
            ldsm4(aA + 4352 + ko, a1);
            ldsm4(aB + ko, b0);
            ldsm4(aB + 4352 + ko, b1r);
            mma16816h(acc[0][0], a0, b0); mma16816h(acc[0][1], a0, b0 + 2);
            mma16816h(acc[0][2], a0, b1r); mma16816h(acc[0][3], a0, b1r + 2);
            mma16816h(acc[1][0], a1, b0); mma16816h(acc[1][1], a1, b0 + 2);
            mma16816h(acc[1][2], a1, b1r); mma16816h(acc[1][3], a1, b1r + 2);
        }
    }
    {
        float bv[8];
        #pragma unroll
        for (int nt = 0; nt < 4; ++nt) {
            bv[nt * 2]     = b1[j0 + nt * 8 + 2 * tq];
            bv[nt * 2 + 1] = b1[j0 + nt * 8 + 2 * tq + 1];
        }
        #pragma unroll
        for (int mt = 0; mt < 2; ++mt)
            #pragma unroll
            for (int nt = 0; nt < 4; ++nt) {
                int col = j0 + nt * 8 + 2 * tq;
                int row0 = l0w + mt * 16 + g;
                float v0 = fmaxf(acc[mt][nt][0] + bv[nt * 2], 0.0f);
                float v1 = fmaxf(acc[mt][nt][1] + bv[nt * 2 + 1], 0.0f);
                float v2 = fmaxf(acc[mt][nt][2] + bv[nt * 2], 0.0f);
                float v3 = fmaxf(acc[mt][nt][3] + bv[nt * 2 + 1], 0.0f);
                *reinterpret_cast<uint32_t*>(sm + K1_P1 + row0 * PITCHB + col * 2) = pack_h2(v0, v1);
                *reinterpret_cast<uint32_t*>(sm + K1_P1 + (row0 + 8) * PITCHB + col * 2) = pack_h2(v2, v3);
            }
    }
    __syncthreads();

    #pragma unroll
    for (int cch = 0; cch < 2; ++cch) {
        for (int i = tid; i < 8192; i += 256) {
            int kk = i >> 7, j = i & 127;
            stg[kk * 129 + j] = W2[(size_t)(cch * 64 + kk) * DH + j];
        }
        __syncthreads();
        for (int i = tid; i < 8192; i += 256) {
            int j = i >> 6, kk = i & 63;
            *reinterpret_cast<__half*>(sm + K1_P2 + j * PITCHB + (cch * 64 + kk) * 2) =
                __float2half(stg[kk * 129 + j]);
        }
        __syncthreads();
    }

    #pragma unroll
    for (int mt = 0; mt < 2; ++mt)
        #pragma unroll
        for (int nt = 0; nt < 4; ++nt)
            #pragma unroll
            for (int q = 0; q < 4; ++q) acc[mt][nt][q] = 0.0f;

    {
        const uint32_t aA = sb + K1_P1 + aoffA;
        const uint32_t aB = sb + K1_P2 + aoffB;
        #pragma unroll
        for (int ks = 0; ks < 8; ++ks) {
            const uint32_t ko = ks * 32;
            uint32_t a0[4], a1[4], b0[4], b1r[4];
            ldsm4(aA + ko, a0);
            ldsm4(aA + 4352 + ko, a1);
            ldsm4(aB + ko, b0);
            ldsm4(aB + 4352 + ko, b1r);
            mma16816h(acc[0][0], a0, b0); mma16816h(acc[0][1], a0, b0 + 2);
            mma16816h(acc[0][2], a0, b1r); mma16816h(acc[0][3], a0, b1r + 2);
            mma16816h(acc[1][0], a1, b0); mma16816h(acc[1][1], a1, b0 + 2);
            mma16816h(acc[1][2], a1, b1r); mma16816h(acc[1][3], a1, b1r + 2);
        }
    }
    {
        float bv[8];
        #pragma unroll
        for (int nt = 0; nt < 4; ++nt) {
            bv[nt * 2]     = b2[j0 + nt * 8 + 2 * tq];
            bv[nt * 2 + 1] = b2[j0 + nt * 8 + 2 * tq + 1];
        }
        size_t rowg0 = (size_t)n * LL + lh * 64;
        #pragma unroll
        for (int mt = 0; mt < 2; ++mt)
            #pragma unroll
            for (int nt = 0; nt < 4; ++nt) {
                int col = j0 + nt * 8 + 2 * tq;
                size_t row0 = rowg0 + l0w + mt * 16 + g;
                float v0 = fmaxf(acc[mt][nt][0] + bv[nt * 2], 0.0f);
                float v1 = fmaxf(acc[mt][nt][1] + bv[nt * 2 + 1], 0.0f);
                float v2 = fmaxf(acc[mt][nt][2] + bv[nt * 2], 0.0f);
                float v3 = fmaxf(acc[mt][nt][3] + bv[nt * 2 + 1], 0.0f);
                *reinterpret_cast<uint32_t*>(&g_h2f16[row0 * DH + col]) = pack_h2(v0, v1);
                *reinterpret_cast<uint32_t*>(&g_h2f16[(row0 + 8) * DH + col]) = pack_h2(v2, v3);
            }
    }
}

// ---------------------------------------------------------------------------
// k2: persistent, 296 CTAs. fp16 MMA + B-frag prefetch + deferred reduction.
// One __syncthreads per tile; issue_A placed AFTER the barrier (fixes the
// R15 A-buffer WAR race) with cp.async.wait_group 0 at the loop top.
// ---------------------------------------------------------------------------
#define OFF_A0   0
#define OFF_A1   34816
#define OFF_B    69632
#define OFF_IDX  104448      // 128 ints
#define OFF_LC   104960
#define OFF_SS   104976      // 2 banks x 256 f
#define OFF_DD   107024      // 2 banks x 256 f
#define K2_SMEM  109072

#define NCTA 296
#define NTILES 8192

__device__ __forceinline__ void issue_A(uint32_t sb, int buf, int h, int tid) {
    uint32_t base = sb + (buf ? OFF_A1 : OFF_A0);
    const __half* src0 = g_W3f16 + (size_t)h * DIN * DH;
    #pragma unroll
    for (int i = tid; i < 2048; i += 256) {
        int r = i >> 4, c = i & 15;
        CP_ASYNC16(base + r * PITCHB + c * 16, src0 + r * 128 + c * 8);
    }
}

// warp0 reduce of bank for tile tp -> out[n,h]
__device__ __forceinline__ void reduce_tile(
    const float* sS, const float* sD, int tp, int lane,
    const float* __restrict__ tbias, float* __restrict__ out)
{
    const int bank = (tp & 1) << 8;
    float r = 0.0f;
    #pragma unroll
    for (int q = 0; q < 4; ++q) {
        int f = lane + q * 32;
        int i0 = (f >> 5) * 32 + ((f >> 3) & 3) * 8 + (f & 7);
        float ss = sS[bank + i0] + sS[bank + i0 + 128];
        float dd = sD[bank + i0] + sD[bank + i0 + 128];
        r += __fdividef(dd, ss);
    }
    #pragma unroll
    for (int o = 16; o; o >>= 1) r += __shfl_xor_sync(0xffffffffu, r, o);
    if (lane == 0) {
        int pn = tp >> 7, ph = tp & 127;
        out[pn * DH + ph] = fmaxf(r + tbias[ph], 0.0f);
    }
}

__global__ void __launch_bounds__(256, 2) k2_filter(
    const float* __restrict__ x, const float* __restrict__ mask,
    const float* __restrict__ tbias, float* __restrict__ out)
{
    char* sm = dynsm;
    const uint32_t sb = smem_u32(sm);
    int* sIdx = reinterpret_cast<int*>(sm + OFF_IDX);
    int* sLc  = reinterpret_cast<int*>(sm + OFF_LC);
    float* sS = reinterpret_cast<float*>(sm + OFF_SS);
    float* sD = reinterpret_cast<float*>(sm + OFF_DD);

    const int tid  = threadIdx.x;
    const int lane = tid & 31, wid = tid >> 5;
    const int g = lane >> 2, tq = lane & 3;
    const int mh = wid & 3, nh = wid >> 2;
    const int f0 = mh * 32, l0 = nh * 64;

    const int c  = blockIdx.x;
    const int ts = (int)(((long long)c * NTILES) / NCTA);
    const int te = (int)(((long long)(c + 1) * NTILES) / NCTA);

    const int rr = lane & 7, mm = lane >> 3;
    const uint32_t aoff = (uint32_t)((f0 + (mm & 1) * 8 + rr) * PITCHB + (mm >> 1) * 16);
    const uint32_t boff = (uint32_t)((l0 + (mm >> 1) * 8 + rr) * PITCHB + (mm & 1) * 16);
    const uint32_t aB = sb + OFF_B + boff;

    issue_A(sb, 0, ts & 127, tid);
    CP_COMMIT();

    int curn = -1, buf = 0, Lc = 0;
    uint32_t xr2[4][8];
    uint32_t vm = 0;
    float invF = 0.0f;

    for (int t = ts; t < te; ++t) {
        const int n = t >> 7, h = t & 127;
        const int bank = (t & 1) << 8;

        if (n != curn) {
            curn = n;
            if (wid == 0) {
                int base = 0;
                #pragma unroll
                for (int cc = 0; cc < 4; ++cc) {
                    float mv = mask[n * LL + cc * 32 + lane];
                    unsigned bal = __ballot_sync(0xffffffffu, mv != 0.0f);
                    int pos = __popc(bal & ((1u << lane) - 1u));
                    if (mv != 0.0f) sIdx[base + pos] = cc * 32 + lane;
                    base += __popc(bal);
                }
                if (lane == 0) *sLc = base;
            }
            __syncthreads();   // all warps done with tile t-1; sIdx/Lc visible
            Lc = *sLc;
            {
                const uint4* bsrc = reinterpret_cast<const uint4*>(g_h2f16 + (size_t)n * LL * DH);
                #pragma unroll
                for (int i = tid; i < 2048; i += 256) {
                    int r = i >> 4, cc = i & 15;
                    uint4 v = make_uint4(0, 0, 0, 0);
                    if (r < Lc) v = bsrc[sIdx[r] * 16 + cc];
                    *reinterpret_cast<uint4*>(sm + OFF_B + r * PITCHB + cc * 16) = v;
                }
            }
            {
                const float* xp = x + (size_t)n * LL * DIN;
                vm = 0;
                #pragma unroll
                for (int nt = 0; nt < 8; ++nt) {
                    int le = l0 + nt * 8 + 2 * tq;
                    int lo = le + 1;
                    bool ve = le < Lc, vo = lo < Lc;
                    if (ve) vm |= 1u << (2 * nt);
                    if (vo) vm |= 1u << (2 * nt + 1);
                    int ie = ve ? sIdx[le] : 0;
                    int io = vo ? sIdx[lo] : 0;
                    #pragma unroll
                    for (int fr = 0; fr < 4; ++fr) {
                        int f = f0 + (fr >> 1) * 16 + (fr & 1) * 8 + g;
                        float xe = ve ? xp[(size_t)ie * DIN + f] : 0.0f;
                        float xo = vo ? xp[(size_t)io * DIN + f] : 0.0f;
                        xr2[fr][nt] = pack_h2(xe, xo);
                    }
                }
                uint32_t anyg = (vm | (vm >> 1)) & 0x5555u;
                uint32_t execMask = anyg | (anyg << 1);
                invF = (float)__popc(execMask & ~vm & 0xFFFFu);
            }
        }

        CP_WAIT0();        // A(t) copies (this thread's) complete
        __syncthreads();   // A(t) + B visible to all; ALL warps done reading
                           // buf^1 (tile t-1's A) and writing bank(t-1) s/d

        // deferred reduction of tile t-1 on warp0, overlapped with others' MMA
        if (wid == 0 && t > ts)
            reduce_tile(sS, sD, t - 1, lane, tbias, out);

        // prefetch next A into buf^1 — safe: all t-1 reads of it finished above
        if (t + 1 < te) {
            issue_A(sb, buf ^ 1, (t + 1) & 127, tid);
            CP_COMMIT();
        }

        const uint32_t aA = sb + (buf ? OFF_A1 : OFF_A0) + aoff;

        float acc[2][8][4];
        #pragma unroll
        for (int mt = 0; mt < 2; ++mt)
            #pragma unroll
            for (int nt = 0; nt < 8; ++nt)
                #pragma unroll
                for (int q = 0; q < 4; ++q) acc[mt][nt][q] = 0.0f;

        #pragma unroll
        for (int ks = 0; ks < 8; ++ks) {
            const uint32_t ko = ks * 32;
            uint32_t ah0[4], ah1[4], bhd[2][4];
            ldsm4(aA + ko, ah0);
            ldsm4(aA + 4352 + ko, ah1);
            ldsm4(aB + ko, bhd[0]);            // p=0 prefetch (B tail zero-filled: safe)
            #pragma unroll
            for (int p = 0; p < 4; ++p) {
                if (p < 3) ldsm4(aB + (p + 1) * 4352 + ko, bhd[(p + 1) & 1]);
                const uint32_t* bh = bhd[p & 1];
                int lp = l0 + p * 16;
                if (lp < Lc) {
                    mma16816h(acc[0][2 * p], ah0, bh);
                    mma16816h(acc[1][2 * p], ah1, bh);
                    if (lp + 8 < Lc) {
                        mma16816h(acc[0][2 * p + 1], ah0, bh + 2);
                        mma16816h(acc[1][2 * p + 1], ah1, bh + 2);
                    }
                }
            }
        }
        buf ^= 1;

        float s[4] = {0, 0, 0, 0}, d[4] = {0, 0, 0, 0};
        #pragma unroll
        for (int nt = 0; nt < 8; ++nt) {
            if (((vm >> (2 * nt)) & 3u) != 0u) {
                float e00 = fex2(acc[0][nt][0]);
                float e01 = fex2(acc[0][nt][1]);
                float e02 = fex2(acc[0][nt][2]);
                float e03 = fex2(acc[0][nt][3]);
                float e10 = fex2(acc[1][nt][0]);
                float e11 = fex2(acc[1][nt][1]);
                float e12 = fex2(acc[1][nt][2]);
                float e13 = fex2(acc[1][nt][3]);
                float2 x0 = __half22float2(*reinterpret_cast<const __half2*>(&xr2[0][nt]));
                float2 x1 = __half22float2(*reinterpret_cast<const __half2*>(&xr2[1][nt]));
                float2 x2 = __half22float2(*reinterpret_cast<const __half2*>(&xr2[2][nt]));
                float2 x3 = __half22float2(*reinterpret_cast<const __half2*>(&xr2[3][nt]));
                s[0] += e00 + e01;
                s[1] += e02 + e03;
                s[2] += e10 + e11;
                s[3] += e12 + e13;
                d[0] = fmaf(x0.x, e00, d[0]); d[0] = fmaf(x0.y, e01, d[0]);
                d[1] = fmaf(x1.x, e02, d[1]); d[1] = fmaf(x1.y, e03, d[1]);
                d[2] = fmaf(x2.x, e10, d[2]); d[2] = fmaf(x2.y, e11, d[2]);
                d[3] = fmaf(x3.x, e12, d[3]); d[3] = fmaf(x3.y, e13, d[3]);
            }
        }
        #pragma unroll
        for (int fr = 0; fr < 4; ++fr) s[fr] -= invF;

        #pragma unroll
        for (int fr = 0; fr < 4; ++fr) {
            s[fr] += __shfl_xor_sync(0xffffffffu, s[fr], 1);
            s[fr] += __shfl_xor_sync(0xffffffffu, s[fr], 2);
            d[fr] += __shfl_xor_sync(0xffffffffu, d[fr], 1);
            d[fr] += __shfl_xor_sync(0xffffffffu, d[fr], 2);
        }
        // banked write, NO sync: reduced after next tile's loop-top barrier
        if (tq == 0) {
            #pragma unroll
            for (int fr = 0; fr < 4; ++fr) {
                sS[bank + wid * 32 + fr * 8 + g] = s[fr];
                sD[bank + wid * 32 + fr * 8 + g] = d[fr];
            }
        }
    }

    // final tile's reduction
    __syncthreads();
    if (wid == 0)
        reduce_tile(sS, sD, te - 1, lane, tbias, out);
}

// ---------------------------------------------------------------------------
extern "C" void kernel_launch(void* const* d_in, const int* in_sizes, int n_in,
                              void* d_out, int out_size) {
    const float* x    = (const float*)d_in[0];
    const float* mask = (const float*)d_in[1];
    const float* W1   = (const float*)d_in[2];
    const float* b1   = (const float*)d_in[3];
    const float* W2   = (const float*)d_in[4];
    const float* b2   = (const float*)d_in[5];
    const float* W3   = (const float*)d_in[6];
    // d_in[7] = b3: per-feature constant over l -> cancels in the softmax
    const float* tb   = (const float*)d_in[8];
    float* out = (float*)d_out;

    cudaFuncSetAttribute(k01,       cudaFuncAttributeMaxDynamicSharedMemorySize, K01_SMEM);
    cudaFuncSetAttribute(k2_filter, cudaFuncAttributeMaxDynamicSharedMemorySize, K2_SMEM);

    k01<<<640, 256, K01_SMEM>>>(W3, W1, W2, x, b1, b2);
    k2_filter<<<NCTA, 256, K2_SMEM>>>(x, mask, tb, out);
}